// round 1
// baseline (speedup 1.0000x reference)
#include <cuda_runtime.h>
#include <math.h>

// ---------------------------------------------------------------------------
// SplitTransformer: B=8, N=1024, D=768, H=12, DH=64, L=4, MLP=3072
// attn = softmax(PE @ BP^T * D^-0.5)  -- shared across layers & heads
// per layer: xn=LN1(x); v=xn@Wv^T; av=attn@v (batched); o=av@Wout^T+bout;
//            y=LN2(o); h1=gelu(y@W1^T+b1); x' = h1@W2^T+b2 + o
// ---------------------------------------------------------------------------

#define BATCH 8
#define SEQ   1024
#define DIM   768
#define NLAYER 4
#define MLPD  3072
#define MTOT  (BATCH*SEQ)   // 8192

// scratch (no cudaMalloc allowed)
__device__ float g_attn[BATCH * SEQ * SEQ];      // 32 MiB
__device__ float g_xn  [MTOT * DIM];
__device__ float g_v   [MTOT * DIM];
__device__ float g_av  [MTOT * DIM];
__device__ float g_o   [MTOT * DIM];
__device__ float g_y   [MTOT * DIM];
__device__ float g_h1  [MTOT * MLPD];            // 96 MiB
__device__ float g_xb  [MTOT * DIM];

// ---------------------------------------------------------------------------
// GEMM: C = A[M,K] * op(B) (+bias)(+epilogue), fp32, 128x128x8 tiles,
// 256 threads, 8x8 per-thread, double-buffered smem.
// TRANSB=true : B is [N,K] row-major (C = A B^T)
// TRANSB=false: B is [K,N] row-major (C = A B)
// EPI: 0 = scale+bias, 1 = bias+GELU(exact), 2 = bias+residual add
// ---------------------------------------------------------------------------
template<bool TRANSB, int EPI>
__global__ __launch_bounds__(256, 2)
void gemm_kernel(const float* __restrict__ A, const float* __restrict__ Bm,
                 float* __restrict__ C, int M, int N, int K,
                 const float* __restrict__ bias, const float* __restrict__ res,
                 float scale,
                 long long sA, long long sB, long long sC)
{
    A  += (long long)blockIdx.z * sA;
    Bm += (long long)blockIdx.z * sB;
    C  += (long long)blockIdx.z * sC;

    const int tid = threadIdx.x;
    const int tx = tid & 15;          // 0..15 -> n sub-tile
    const int ty = tid >> 4;          // 0..15 -> m sub-tile
    const int m0 = blockIdx.y * 128;
    const int n0 = blockIdx.x * 128;

    __shared__ float As[2][8][128];
    __shared__ float Bs[2][8][128];

    // global->smem mapping (A and transposed-B share the same pattern)
    const int ra = tid >> 1;          // row within tile (0..127)
    const int ka = (tid & 1) * 4;     // k offset (0 or 4)
    const int kb_nn = tid >> 5;       // 0..7
    const int nb_nn = (tid & 31) * 4; // 0..124

    const float* Aptr = A + (long long)(m0 + ra) * K + ka;
    const float* Bptr;
    if (TRANSB) Bptr = Bm + (long long)(n0 + ra) * K + ka;
    else        Bptr = Bm + (long long)kb_nn * N + n0 + nb_nn;

    float acc[8][8];
    #pragma unroll
    for (int i = 0; i < 8; i++)
        #pragma unroll
        for (int j = 0; j < 8; j++) acc[i][j] = 0.f;

    // prologue: tile 0 -> smem buf 0
    float4 aReg = *(const float4*)Aptr;
    float4 bReg;
    if (TRANSB) bReg = *(const float4*)Bptr;
    else        bReg = *(const float4*)Bptr;

    As[0][ka + 0][ra] = aReg.x; As[0][ka + 1][ra] = aReg.y;
    As[0][ka + 2][ra] = aReg.z; As[0][ka + 3][ra] = aReg.w;
    if (TRANSB) {
        Bs[0][ka + 0][ra] = bReg.x; Bs[0][ka + 1][ra] = bReg.y;
        Bs[0][ka + 2][ra] = bReg.z; Bs[0][ka + 3][ra] = bReg.w;
    } else {
        *(float4*)&Bs[0][kb_nn][nb_nn] = bReg;
    }
    __syncthreads();

    const int nk = K >> 3;
    int buf = 0;
    for (int kt = 0; kt < nk; ++kt) {
        // prefetch next tile into registers while computing
        if (kt + 1 < nk) {
            aReg = *(const float4*)(Aptr + (kt + 1) * 8);
            if (TRANSB) bReg = *(const float4*)(Bptr + (kt + 1) * 8);
            else        bReg = *(const float4*)(Bptr + (long long)(kt + 1) * 8 * N);
        }
        #pragma unroll
        for (int k = 0; k < 8; ++k) {
            float a[8], b[8];
            *(float4*)(a)     = *(const float4*)&As[buf][k][ty * 8];
            *(float4*)(a + 4) = *(const float4*)&As[buf][k][ty * 8 + 4];
            *(float4*)(b)     = *(const float4*)&Bs[buf][k][tx * 8];
            *(float4*)(b + 4) = *(const float4*)&Bs[buf][k][tx * 8 + 4];
            #pragma unroll
            for (int i = 0; i < 8; i++)
                #pragma unroll
                for (int j = 0; j < 8; j++)
                    acc[i][j] = fmaf(a[i], b[j], acc[i][j]);
        }
        if (kt + 1 < nk) {
            const int nb = buf ^ 1;
            As[nb][ka + 0][ra] = aReg.x; As[nb][ka + 1][ra] = aReg.y;
            As[nb][ka + 2][ra] = aReg.z; As[nb][ka + 3][ra] = aReg.w;
            if (TRANSB) {
                Bs[nb][ka + 0][ra] = bReg.x; Bs[nb][ka + 1][ra] = bReg.y;
                Bs[nb][ka + 2][ra] = bReg.z; Bs[nb][ka + 3][ra] = bReg.w;
            } else {
                *(float4*)&Bs[nb][kb_nn][nb_nn] = bReg;
            }
            __syncthreads();
            buf = nb;
        }
    }

    // epilogue
    const int cm = m0 + ty * 8;
    const int cn = n0 + tx * 8;
    float bv[8];
    if (bias) {
        #pragma unroll
        for (int j = 0; j < 8; j++) bv[j] = bias[cn + j];
    } else {
        #pragma unroll
        for (int j = 0; j < 8; j++) bv[j] = 0.f;
    }
    #pragma unroll
    for (int i = 0; i < 8; i++) {
        const long long rowoff = (long long)(cm + i) * N + cn;
        float out[8];
        #pragma unroll
        for (int j = 0; j < 8; j++) {
            float val = acc[i][j] * scale + bv[j];
            if (EPI == 1) val = 0.5f * val * (1.0f + erff(val * 0.70710678118654752f));
            out[j] = val;
        }
        if (EPI == 2) {
            float4 r0 = *(const float4*)&res[rowoff];
            float4 r1 = *(const float4*)&res[rowoff + 4];
            out[0] += r0.x; out[1] += r0.y; out[2] += r0.z; out[3] += r0.w;
            out[4] += r1.x; out[5] += r1.y; out[6] += r1.z; out[7] += r1.w;
        }
        *(float4*)&C[rowoff]     = make_float4(out[0], out[1], out[2], out[3]);
        *(float4*)&C[rowoff + 4] = make_float4(out[4], out[5], out[6], out[7]);
    }
}

// ---------------------------------------------------------------------------
// Row softmax over 1024 columns; one block (256 thr) per row, in-place.
// ---------------------------------------------------------------------------
__global__ void softmax_kernel(float* __restrict__ data)
{
    const long long row = blockIdx.x;
    float* p = data + row * 1024;
    const int t = threadIdx.x;

    float4 v = *(float4*)(p + t * 4);
    float mx = fmaxf(fmaxf(v.x, v.y), fmaxf(v.z, v.w));

    __shared__ float sh[8];
    #pragma unroll
    for (int o = 16; o; o >>= 1) mx = fmaxf(mx, __shfl_xor_sync(0xffffffffu, mx, o));
    if ((t & 31) == 0) sh[t >> 5] = mx;
    __syncthreads();
    if (t < 32) {
        float m = (t < 8) ? sh[t] : -3.4e38f;
        #pragma unroll
        for (int o = 4; o; o >>= 1) m = fmaxf(m, __shfl_xor_sync(0xffffffffu, m, o));
        if (t == 0) sh[0] = m;
    }
    __syncthreads();
    mx = sh[0];
    __syncthreads();

    v.x = expf(v.x - mx); v.y = expf(v.y - mx);
    v.z = expf(v.z - mx); v.w = expf(v.w - mx);
    float s = v.x + v.y + v.z + v.w;
    #pragma unroll
    for (int o = 16; o; o >>= 1) s += __shfl_xor_sync(0xffffffffu, s, o);
    if ((t & 31) == 0) sh[t >> 5] = s;
    __syncthreads();
    if (t < 32) {
        float m = (t < 8) ? sh[t] : 0.f;
        #pragma unroll
        for (int o = 4; o; o >>= 1) m += __shfl_xor_sync(0xffffffffu, m, o);
        if (t == 0) sh[0] = m;
    }
    __syncthreads();
    const float inv = 1.0f / sh[0];
    v.x *= inv; v.y *= inv; v.z *= inv; v.w *= inv;
    *(float4*)(p + t * 4) = v;
}

// ---------------------------------------------------------------------------
// LayerNorm over 768 columns; one block (256 thr, 3 elems/thr) per row.
// ---------------------------------------------------------------------------
__global__ void ln_kernel(const float* __restrict__ in, float* __restrict__ out,
                          const float* __restrict__ w, const float* __restrict__ b)
{
    const long long row = blockIdx.x;
    const float* p = in  + row * DIM;
    float*       q = out + row * DIM;
    const int t = threadIdx.x;

    float x0 = p[t], x1 = p[t + 256], x2 = p[t + 512];
    float s  = x0 + x1 + x2;
    float ss = x0 * x0 + x1 * x1 + x2 * x2;

    __shared__ float shs[8], shss[8];
    #pragma unroll
    for (int o = 16; o; o >>= 1) {
        s  += __shfl_xor_sync(0xffffffffu, s,  o);
        ss += __shfl_xor_sync(0xffffffffu, ss, o);
    }
    if ((t & 31) == 0) { shs[t >> 5] = s; shss[t >> 5] = ss; }
    __syncthreads();
    if (t < 32) {
        s  = (t < 8) ? shs[t]  : 0.f;
        ss = (t < 8) ? shss[t] : 0.f;
        #pragma unroll
        for (int o = 4; o; o >>= 1) {
            s  += __shfl_xor_sync(0xffffffffu, s,  o);
            ss += __shfl_xor_sync(0xffffffffu, ss, o);
        }
        if (t == 0) { shs[0] = s; shss[0] = ss; }
    }
    __syncthreads();
    const float mean = shs[0] * (1.f / DIM);
    const float var  = shss[0] * (1.f / DIM) - mean * mean;
    const float r    = rsqrtf(var + 1e-5f);

    q[t]       = (x0 - mean) * r * w[t]       + b[t];
    q[t + 256] = (x1 - mean) * r * w[t + 256] + b[t + 256];
    q[t + 512] = (x2 - mean) * r * w[t + 512] + b[t + 512];
}

// ---------------------------------------------------------------------------
extern "C" void kernel_launch(void* const* d_in, const int* in_sizes, int n_in,
                              void* d_out, int out_size)
{
    const float* x    = (const float*)d_in[0];
    const float* pe   = (const float*)d_in[1];
    const float* bp   = (const float*)d_in[2];
    const float* ln1w = (const float*)d_in[3];
    const float* ln1b = (const float*)d_in[4];
    const float* Wqkv = (const float*)d_in[5];   // [L, 2304, 768]
    const float* Wout = (const float*)d_in[6];   // [L, 768, 768]
    const float* bout = (const float*)d_in[7];
    const float* ln2w = (const float*)d_in[8];
    const float* ln2b = (const float*)d_in[9];
    const float* W1   = (const float*)d_in[10];  // [L, 3072, 768]
    const float* b1   = (const float*)d_in[11];
    const float* W2   = (const float*)d_in[12];  // [L, 768, 3072]
    const float* b2   = (const float*)d_in[13];

    float *attn, *xn, *v, *av, *o, *y, *h1, *xb;
    cudaGetSymbolAddress((void**)&attn, g_attn);
    cudaGetSymbolAddress((void**)&xn,   g_xn);
    cudaGetSymbolAddress((void**)&v,    g_v);
    cudaGetSymbolAddress((void**)&av,   g_av);
    cudaGetSymbolAddress((void**)&o,    g_o);
    cudaGetSymbolAddress((void**)&y,    g_y);
    cudaGetSymbolAddress((void**)&h1,   g_h1);
    cudaGetSymbolAddress((void**)&xb,   g_xb);

    const float scale = 0.03608439182435161f;   // 768^-0.5

    // dots = PE[8192,768] @ BP[1024,768]^T * scale ; then softmax rows
    gemm_kernel<true, 0><<<dim3(SEQ / 128, MTOT / 128, 1), 256>>>(
        pe, bp, attn, MTOT, SEQ, DIM, nullptr, nullptr, scale, 0, 0, 0);
    softmax_kernel<<<MTOT, 256>>>(attn);

    const float* xc = x;
    for (int l = 0; l < NLAYER; ++l) {
        const float* Wv = Wqkv + (long long)l * 3 * DIM * DIM + (long long)2 * DIM * DIM;

        ln_kernel<<<MTOT, 256>>>(xc, xn, ln1w + l * DIM, ln1b + l * DIM);

        // v = xn @ Wv^T   [8192,768]
        gemm_kernel<true, 0><<<dim3(DIM / 128, MTOT / 128, 1), 256>>>(
            xn, Wv, v, MTOT, DIM, DIM, nullptr, nullptr, 1.f, 0, 0, 0);

        // av[b] = attn[b] @ v[b]   batched NN
        gemm_kernel<false, 0><<<dim3(DIM / 128, SEQ / 128, BATCH), 256>>>(
            attn, v, av, SEQ, DIM, SEQ, nullptr, nullptr, 1.f,
            (long long)SEQ * SEQ, (long long)SEQ * DIM, (long long)SEQ * DIM);

        // o = av @ Wout^T + bout
        gemm_kernel<true, 0><<<dim3(DIM / 128, MTOT / 128, 1), 256>>>(
            av, Wout + (long long)l * DIM * DIM, o, MTOT, DIM, DIM,
            bout + l * DIM, nullptr, 1.f, 0, 0, 0);

        ln_kernel<<<MTOT, 256>>>(o, y, ln2w + l * DIM, ln2b + l * DIM);

        // h1 = gelu(y @ W1^T + b1)   [8192,3072]
        gemm_kernel<true, 1><<<dim3(MLPD / 128, MTOT / 128, 1), 256>>>(
            y, W1 + (long long)l * MLPD * DIM, h1, MTOT, MLPD, DIM,
            b1 + l * MLPD, nullptr, 1.f, 0, 0, 0);

        // x' = h1 @ W2^T + b2 + o
        float* xdst = (l == NLAYER - 1) ? (float*)d_out : xb;
        gemm_kernel<true, 2><<<dim3(DIM / 128, MTOT / 128, 1), 256>>>(
            h1, W2 + (long long)l * DIM * MLPD, xdst, MTOT, DIM, MLPD,
            b2 + l * DIM, o, 1.f, 0, 0, 0);
        xc = xdst;
    }
}

// round 3
// speedup vs baseline: 2.6731x; 2.6731x over previous
#include <cuda_runtime.h>
#include <cuda_bf16.h>
#include <cstdint>
#include <math.h>

// ---------------------------------------------------------------------------
// SplitTransformer, bf16x3 split-precision GEMMs on mma.sync (HMMA) tensor
// cores. (tcgen05 is unavailable: harness compiles PTX at .target sm_103,
// and tcgen05 requires sm_103a arch-specific PTX.)
// B=8, N=1024, D=768, H=12, DH=64, L=4, MLP=3072
// ---------------------------------------------------------------------------

#define BATCH 8
#define SEQ   1024
#define DIM   768
#define NLAYER 4
#define MLPD  3072
#define MTOT  (BATCH*SEQ)   // 8192

#define BM 128
#define BN 128
#define KC 32               // bf16 k elements per pipeline stage

// smem tile: 128 rows x (KC*2=64B) padded to 80B stride (16B-aligned rows,
// conflict-free ldmatrix: r*80/4 mod 32 distinct over 8 rows)
#define TILE_PAD  80
#define TILE_SZ   (128 * TILE_PAD)          // 10240
#define STAGE_SZ  (4 * TILE_SZ)             // Ah, Al, Bh, Bl
#define SMEM_SZ   (2 * STAGE_SZ)            // 81920

// ---------------- scratch (__device__ globals; no cudaMalloc) --------------
__device__ float          g_dots[MTOT * SEQ];
__device__ __nv_bfloat16  g_attn_h[MTOT * SEQ], g_attn_l[MTOT * SEQ];
__device__ __nv_bfloat16  g_xn_h[MTOT * DIM],  g_xn_l[MTOT * DIM];
__device__ __nv_bfloat16  g_vT_h[DIM * MTOT],  g_vT_l[DIM * MTOT];   // [768, 8192]
__device__ __nv_bfloat16  g_av_h[MTOT * DIM],  g_av_l[MTOT * DIM];
__device__ float          g_o  [MTOT * DIM];
__device__ __nv_bfloat16  g_y_h[MTOT * DIM],   g_y_l[MTOT * DIM];
__device__ __nv_bfloat16  g_h1_h[MTOT * MLPD], g_h1_l[MTOT * MLPD];
__device__ float          g_xb [MTOT * DIM];
__device__ __nv_bfloat16  g_wv_h[NLAYER*DIM*DIM],   g_wv_l[NLAYER*DIM*DIM];
__device__ __nv_bfloat16  g_wo_h[NLAYER*DIM*DIM],   g_wo_l[NLAYER*DIM*DIM];
__device__ __nv_bfloat16  g_w1_h[NLAYER*MLPD*DIM],  g_w1_l[NLAYER*MLPD*DIM];
__device__ __nv_bfloat16  g_w2_h[NLAYER*DIM*MLPD],  g_w2_l[NLAYER*DIM*MLPD];
__device__ __nv_bfloat16  g_pe_h[MTOT * DIM],  g_pe_l[MTOT * DIM];
__device__ __nv_bfloat16  g_bp_h[SEQ * DIM],   g_bp_l[SEQ * DIM];

// ---------------- PTX helpers (all baseline compute_103-legal) -------------
__device__ __forceinline__ uint32_t smem_u32(const void* p) {
    uint32_t a;
    asm("{ .reg .u64 t; cvta.to.shared.u64 t, %1; cvt.u32.u64 %0, t; }" : "=r"(a) : "l"(p));
    return a;
}
__device__ __forceinline__ void cpa16(uint32_t s, const void* g) {
    asm volatile("cp.async.cg.shared.global [%0], [%1], 16;" :: "r"(s), "l"(g));
}
__device__ __forceinline__ void cp_commit() {
    asm volatile("cp.async.commit_group;" ::: "memory");
}
template<int N> __device__ __forceinline__ void cp_wait() {
    asm volatile("cp.async.wait_group %0;" :: "n"(N) : "memory");
}
__device__ __forceinline__ void ldsm4(uint32_t* r, uint32_t a) {
    asm volatile("ldmatrix.sync.aligned.m8n8.x4.shared.b16 {%0,%1,%2,%3}, [%4];"
        : "=r"(r[0]), "=r"(r[1]), "=r"(r[2]), "=r"(r[3]) : "r"(a));
}
__device__ __forceinline__ void mma16816(float* c, const uint32_t* a, const uint32_t* b) {
    asm volatile("mma.sync.aligned.m16n8k16.row.col.f32.bf16.bf16.f32 "
        "{%0,%1,%2,%3}, {%4,%5,%6,%7}, {%8,%9}, {%0,%1,%2,%3};"
        : "+f"(c[0]), "+f"(c[1]), "+f"(c[2]), "+f"(c[3])
        : "r"(a[0]), "r"(a[1]), "r"(a[2]), "r"(a[3]), "r"(b[0]), "r"(b[1]));
}
__device__ __forceinline__ void split2(float v, __nv_bfloat16& h, __nv_bfloat16& l) {
    h = __float2bfloat16_rn(v);
    l = __float2bfloat16_rn(v - __bfloat162float(h));
}

// ---------------------------------------------------------------------------
// EPI: 0 = scale -> fp32 ; 1 = split bf16 hi/lo ; 2 = bias -> fp32 ;
//      3 = bias+gelu -> split ; 4 = bias+residual -> fp32
// C = A[M,K] * B[N,K]^T with bf16x3 split precision (Ah*Bh + Ah*Bl + Al*Bh).
// ---------------------------------------------------------------------------
template<int EPI>
__global__ __launch_bounds__(256)
void mm_kernel(const __nv_bfloat16* __restrict__ Ah, const __nv_bfloat16* __restrict__ Al,
               int ldA, long long sAz,
               const __nv_bfloat16* __restrict__ Bh, const __nv_bfloat16* __restrict__ Bl,
               int ldB, long long sBz,
               float* __restrict__ Cf, __nv_bfloat16* __restrict__ Ch,
               __nv_bfloat16* __restrict__ Cl, int ldC, long long sCz,
               int Kdim, const float* __restrict__ bias, const float* __restrict__ res,
               float scale)
{
    extern __shared__ char smem_raw[];
    const int bz = blockIdx.z;
    Ah += (long long)bz * sAz;  Al += (long long)bz * sAz;
    Bh += (long long)bz * sBz;  Bl += (long long)bz * sBz;
    const long long coff = (long long)bz * sCz;

    const int tid = threadIdx.x;
    const int wid = tid >> 5, lid = tid & 31;
    const int m0 = blockIdx.y * BM;
    const int n0 = blockIdx.x * BN;
    const uint32_t sb = smem_u32(smem_raw);

    // per-thread cp.async coords: 2 chunks per tile per thread
    // u in [0,512): r = u>>2 (row), c = u&3 (16B chunk within KC=32 row)
    // ldmatrix lane address components
    const int arow = (lid & 7) + ((lid >> 3) & 1) * 8;
    const int acolB = ((lid >> 4) & 1) * 16;
    const int brow = (lid & 7) + ((lid >> 4) & 1) * 8;
    const int bcolB = ((lid >> 3) & 1) * 16;
    const int wm = wid & 1;          // 2 m-tiles of 64
    const int wn = wid >> 1;         // 4 n-tiles of 32

    float acc[4][4][4];
    #pragma unroll
    for (int mi = 0; mi < 4; mi++)
        #pragma unroll
        for (int ni = 0; ni < 4; ni++)
            #pragma unroll
            for (int q = 0; q < 4; q++) acc[mi][ni][q] = 0.f;

    const int T = Kdim / KC;

    // ---- issue a full stage of cp.async loads ----
    auto issue = [&](int kt, uint32_t sbuf) {
        const int k0 = kt * KC;
        #pragma unroll
        for (int i = 0; i < 2; i++) {
            const int u = tid + i * 256;
            const int r = u >> 2, c = u & 3;
            const uint32_t soff = r * TILE_PAD + c * 16;
            const size_t ga = (size_t)(m0 + r) * ldA + k0 + c * 8;
            const size_t gb = (size_t)(n0 + r) * ldB + k0 + c * 8;
            cpa16(sbuf + soff,               Ah + ga);
            cpa16(sbuf + TILE_SZ + soff,     Al + ga);
            cpa16(sbuf + 2 * TILE_SZ + soff, Bh + gb);
            cpa16(sbuf + 3 * TILE_SZ + soff, Bl + gb);
        }
    };

    issue(0, sb);
    cp_commit();

    for (int kt = 0; kt < T; kt++) {
        const uint32_t sbuf = sb + (kt & 1) * STAGE_SZ;
        if (kt + 1 < T) {
            issue(kt + 1, sb + ((kt + 1) & 1) * STAGE_SZ);
            cp_commit();
            cp_wait<1>();
        } else {
            cp_wait<0>();
        }
        __syncthreads();

        const uint32_t aB  = sbuf;
        const uint32_t alB = sbuf + TILE_SZ;
        const uint32_t bB  = sbuf + 2 * TILE_SZ;
        const uint32_t blB = sbuf + 3 * TILE_SZ;

        #pragma unroll
        for (int kk = 0; kk < 2; kk++) {           // two k16 halves of KC=32
            const int kByte = kk * 32;
            uint32_t ah[4][4], al_[4][4];
            #pragma unroll
            for (int mi = 0; mi < 4; mi++) {
                const uint32_t off = (uint32_t)(wm * 64 + mi * 16 + arow) * TILE_PAD
                                     + kByte + acolB;
                ldsm4(ah[mi],  aB  + off);
                ldsm4(al_[mi], alB + off);
            }
            uint32_t bh[2][4], bl[2][4];
            #pragma unroll
            for (int nj = 0; nj < 2; nj++) {
                const uint32_t off = (uint32_t)(wn * 32 + nj * 16 + brow) * TILE_PAD
                                     + kByte + bcolB;
                ldsm4(bh[nj], bB  + off);
                ldsm4(bl[nj], blB + off);
            }
            #pragma unroll
            for (int mi = 0; mi < 4; mi++)
                #pragma unroll
                for (int ni = 0; ni < 4; ni++) {
                    const uint32_t* bhp = &bh[ni >> 1][(ni & 1) * 2];
                    const uint32_t* blp = &bl[ni >> 1][(ni & 1) * 2];
                    mma16816(acc[mi][ni], ah[mi],  bhp);
                    mma16816(acc[mi][ni], ah[mi],  blp);
                    mma16816(acc[mi][ni], al_[mi], bhp);
                }
        }
        __syncthreads();
    }

    // ---- epilogue ----
    const int l4 = lid >> 2;
    const int lp = (lid & 3) * 2;
    #pragma unroll
    for (int mi = 0; mi < 4; mi++) {
        #pragma unroll
        for (int ni = 0; ni < 4; ni++) {
            const int col  = n0 + wn * 32 + ni * 8 + lp;
            const int rowA = m0 + wm * 64 + mi * 16 + l4;
            float* a = acc[mi][ni];
            #pragma unroll
            for (int h = 0; h < 2; h++) {
                const int row = rowA + h * 8;
                float v0 = a[h * 2], v1 = a[h * 2 + 1];
                if (EPI == 0) { v0 *= scale; v1 *= scale; }
                if (EPI == 2 || EPI == 3 || EPI == 4) {
                    v0 += __ldg(bias + col);
                    v1 += __ldg(bias + col + 1);
                }
                if (EPI == 3) {
                    v0 = 0.5f * v0 * (1.0f + erff(v0 * 0.70710678118654752f));
                    v1 = 0.5f * v1 * (1.0f + erff(v1 * 0.70710678118654752f));
                }
                const size_t cbase = (size_t)row * ldC + col + coff;
                if (EPI == 4) {
                    float2 rr = *(const float2*)(res + cbase);
                    v0 += rr.x; v1 += rr.y;
                }
                if (EPI == 0 || EPI == 2 || EPI == 4) {
                    *(float2*)(Cf + cbase) = make_float2(v0, v1);
                } else {
                    __nv_bfloat16 h0, l0, h1_, l1_;
                    split2(v0, h0, l0); split2(v1, h1_, l1_);
                    __nv_bfloat162 hh; hh.x = h0; hh.y = h1_;
                    __nv_bfloat162 ll; ll.x = l0; ll.y = l1_;
                    *(__nv_bfloat162*)(Ch + cbase) = hh;
                    *(__nv_bfloat162*)(Cl + cbase) = ll;
                }
            }
        }
    }
}

// ---------------------------------------------------------------------------
// fp32 -> bf16 hi/lo split (contiguous)
__global__ void split_kernel(const float* __restrict__ in, __nv_bfloat16* __restrict__ h,
                             __nv_bfloat16* __restrict__ l, int n4)
{
    int i = blockIdx.x * blockDim.x + threadIdx.x;
    if (i >= n4) return;
    float4 v = *(const float4*)(in + i * 4);
    __nv_bfloat16 h0,l0,h1,l1,h2,l2,h3,l3;
    split2(v.x,h0,l0); split2(v.y,h1,l1); split2(v.z,h2,l2); split2(v.w,h3,l3);
    __nv_bfloat162 a; a.x=h0; a.y=h1; __nv_bfloat162 b; b.x=h2; b.y=h3;
    __nv_bfloat162 c; c.x=l0; c.y=l1; __nv_bfloat162 d; d.x=l2; d.y=l3;
    *(uint2*)(h + i * 4) = make_uint2(*(uint32_t*)&a, *(uint32_t*)&b);
    *(uint2*)(l + i * 4) = make_uint2(*(uint32_t*)&c, *(uint32_t*)&d);
}

// Wv slice split: Wqkv[l, 1536:2304, :] for l in 0..3
__global__ void split_wv_kernel(const float* __restrict__ Wqkv,
                                __nv_bfloat16* __restrict__ h, __nv_bfloat16* __restrict__ l)
{
    int i = blockIdx.x * blockDim.x + threadIdx.x;
    const int per = DIM * DIM / 4;
    if (i >= NLAYER * per) return;
    int li = i / per, rem = i - li * per;
    const float* src = Wqkv + (size_t)li * 3 * DIM * DIM + (size_t)2 * DIM * DIM + rem * 4;
    float4 v = *(const float4*)src;
    __nv_bfloat16 h0,l0,h1,l1,h2,l2,h3,l3;
    split2(v.x,h0,l0); split2(v.y,h1,l1); split2(v.z,h2,l2); split2(v.w,h3,l3);
    __nv_bfloat162 a; a.x=h0; a.y=h1; __nv_bfloat162 b; b.x=h2; b.y=h3;
    __nv_bfloat162 c; c.x=l0; c.y=l1; __nv_bfloat162 d; d.x=l2; d.y=l3;
    *(uint2*)(h + i * 4) = make_uint2(*(uint32_t*)&a, *(uint32_t*)&b);
    *(uint2*)(l + i * 4) = make_uint2(*(uint32_t*)&c, *(uint32_t*)&d);
}

// ---------------------------------------------------------------------------
// softmax over 1024 cols, fp32 in -> bf16 hi/lo out
__global__ void softmax_kernel(const float* __restrict__ dots,
                               __nv_bfloat16* __restrict__ oh, __nv_bfloat16* __restrict__ ol)
{
    const size_t row = blockIdx.x;
    const float* p = dots + row * SEQ;
    const int t = threadIdx.x;

    float4 v = *(const float4*)(p + t * 4);
    float mx = fmaxf(fmaxf(v.x, v.y), fmaxf(v.z, v.w));
    __shared__ float sh[8];
    #pragma unroll
    for (int o = 16; o; o >>= 1) mx = fmaxf(mx, __shfl_xor_sync(0xffffffffu, mx, o));
    if ((t & 31) == 0) sh[t >> 5] = mx;
    __syncthreads();
    if (t < 32) {
        float m = (t < 8) ? sh[t] : -3.4e38f;
        #pragma unroll
        for (int o = 4; o; o >>= 1) m = fmaxf(m, __shfl_xor_sync(0xffffffffu, m, o));
        if (t == 0) sh[0] = m;
    }
    __syncthreads();
    mx = sh[0];
    __syncthreads();

    v.x = expf(v.x - mx); v.y = expf(v.y - mx);
    v.z = expf(v.z - mx); v.w = expf(v.w - mx);
    float s = v.x + v.y + v.z + v.w;
    #pragma unroll
    for (int o = 16; o; o >>= 1) s += __shfl_xor_sync(0xffffffffu, s, o);
    if ((t & 31) == 0) sh[t >> 5] = s;
    __syncthreads();
    if (t < 32) {
        float m = (t < 8) ? sh[t] : 0.f;
        #pragma unroll
        for (int o = 4; o; o >>= 1) m += __shfl_xor_sync(0xffffffffu, m, o);
        if (t == 0) sh[0] = m;
    }
    __syncthreads();
    const float inv = 1.0f / sh[0];
    v.x *= inv; v.y *= inv; v.z *= inv; v.w *= inv;

    __nv_bfloat16 h0,l0,h1,l1,h2,l2,h3,l3;
    split2(v.x,h0,l0); split2(v.y,h1,l1); split2(v.z,h2,l2); split2(v.w,h3,l3);
    __nv_bfloat162 a; a.x=h0; a.y=h1; __nv_bfloat162 b; b.x=h2; b.y=h3;
    __nv_bfloat162 c; c.x=l0; c.y=l1; __nv_bfloat162 d; d.x=l2; d.y=l3;
    *(uint2*)(oh + row * SEQ + t * 4) = make_uint2(*(uint32_t*)&a, *(uint32_t*)&b);
    *(uint2*)(ol + row * SEQ + t * 4) = make_uint2(*(uint32_t*)&c, *(uint32_t*)&d);
}

// ---------------------------------------------------------------------------
// LayerNorm(768) -> bf16 hi/lo
__global__ void ln_kernel(const float* __restrict__ in, __nv_bfloat16* __restrict__ oh,
                          __nv_bfloat16* __restrict__ ol,
                          const float* __restrict__ w, const float* __restrict__ b)
{
    const size_t row = blockIdx.x;
    const float* p = in + row * DIM;
    const int t = threadIdx.x;

    float x0 = p[t], x1 = p[t + 256], x2 = p[t + 512];
    float s  = x0 + x1 + x2;
    float ss = x0 * x0 + x1 * x1 + x2 * x2;

    __shared__ float shs[8], shss[8];
    #pragma unroll
    for (int o = 16; o; o >>= 1) {
        s  += __shfl_xor_sync(0xffffffffu, s,  o);
        ss += __shfl_xor_sync(0xffffffffu, ss, o);
    }
    if ((t & 31) == 0) { shs[t >> 5] = s; shss[t >> 5] = ss; }
    __syncthreads();
    if (t < 32) {
        s  = (t < 8) ? shs[t]  : 0.f;
        ss = (t < 8) ? shss[t] : 0.f;
        #pragma unroll
        for (int o = 4; o; o >>= 1) {
            s  += __shfl_xor_sync(0xffffffffu, s,  o);
            ss += __shfl_xor_sync(0xffffffffu, ss, o);
        }
        if (t == 0) { shs[0] = s; shss[0] = ss; }
    }
    __syncthreads();
    const float mean = shs[0] * (1.f / DIM);
    const float var  = shss[0] * (1.f / DIM) - mean * mean;
    const float r    = rsqrtf(var + 1e-5f);

    #pragma unroll
    for (int q = 0; q < 3; q++) {
        int idx = t + q * 256;
        float y = (((q == 0) ? x0 : (q == 1) ? x1 : x2) - mean) * r * w[idx] + b[idx];
        __nv_bfloat16 h, l; split2(y, h, l);
        oh[row * DIM + idx] = h;
        ol[row * DIM + idx] = l;
    }
}

// ---------------------------------------------------------------------------
extern "C" void kernel_launch(void* const* d_in, const int* in_sizes, int n_in,
                              void* d_out, int out_size)
{
    const float* x    = (const float*)d_in[0];
    const float* pe   = (const float*)d_in[1];
    const float* bp   = (const float*)d_in[2];
    const float* ln1w = (const float*)d_in[3];
    const float* ln1b = (const float*)d_in[4];
    const float* Wqkv = (const float*)d_in[5];
    const float* Wout = (const float*)d_in[6];
    const float* bout = (const float*)d_in[7];
    const float* ln2w = (const float*)d_in[8];
    const float* ln2b = (const float*)d_in[9];
    const float* W1   = (const float*)d_in[10];
    const float* b1   = (const float*)d_in[11];
    const float* W2   = (const float*)d_in[12];
    const float* b2   = (const float*)d_in[13];

    cudaFuncSetAttribute(mm_kernel<0>, cudaFuncAttributeMaxDynamicSharedMemorySize, SMEM_SZ);
    cudaFuncSetAttribute(mm_kernel<1>, cudaFuncAttributeMaxDynamicSharedMemorySize, SMEM_SZ);
    cudaFuncSetAttribute(mm_kernel<2>, cudaFuncAttributeMaxDynamicSharedMemorySize, SMEM_SZ);
    cudaFuncSetAttribute(mm_kernel<3>, cudaFuncAttributeMaxDynamicSharedMemorySize, SMEM_SZ);
    cudaFuncSetAttribute(mm_kernel<4>, cudaFuncAttributeMaxDynamicSharedMemorySize, SMEM_SZ);

    float *dots, *o, *xb;
    __nv_bfloat16 *attn_h, *attn_l, *xn_h, *xn_l, *vT_h, *vT_l, *av_h, *av_l;
    __nv_bfloat16 *y_h, *y_l, *h1_h, *h1_l;
    __nv_bfloat16 *wv_h, *wv_l, *wo_h, *wo_l, *w1_h, *w1_l, *w2_h, *w2_l;
    __nv_bfloat16 *pe_h, *pe_l, *bp_h, *bp_l;
    cudaGetSymbolAddress((void**)&dots,   g_dots);
    cudaGetSymbolAddress((void**)&attn_h, g_attn_h); cudaGetSymbolAddress((void**)&attn_l, g_attn_l);
    cudaGetSymbolAddress((void**)&xn_h,   g_xn_h);   cudaGetSymbolAddress((void**)&xn_l,   g_xn_l);
    cudaGetSymbolAddress((void**)&vT_h,   g_vT_h);   cudaGetSymbolAddress((void**)&vT_l,   g_vT_l);
    cudaGetSymbolAddress((void**)&av_h,   g_av_h);   cudaGetSymbolAddress((void**)&av_l,   g_av_l);
    cudaGetSymbolAddress((void**)&o,      g_o);
    cudaGetSymbolAddress((void**)&y_h,    g_y_h);    cudaGetSymbolAddress((void**)&y_l,    g_y_l);
    cudaGetSymbolAddress((void**)&h1_h,   g_h1_h);   cudaGetSymbolAddress((void**)&h1_l,   g_h1_l);
    cudaGetSymbolAddress((void**)&xb,     g_xb);
    cudaGetSymbolAddress((void**)&wv_h,   g_wv_h);   cudaGetSymbolAddress((void**)&wv_l,   g_wv_l);
    cudaGetSymbolAddress((void**)&wo_h,   g_wo_h);   cudaGetSymbolAddress((void**)&wo_l,   g_wo_l);
    cudaGetSymbolAddress((void**)&w1_h,   g_w1_h);   cudaGetSymbolAddress((void**)&w1_l,   g_w1_l);
    cudaGetSymbolAddress((void**)&w2_h,   g_w2_h);   cudaGetSymbolAddress((void**)&w2_l,   g_w2_l);
    cudaGetSymbolAddress((void**)&pe_h,   g_pe_h);   cudaGetSymbolAddress((void**)&pe_l,   g_pe_l);
    cudaGetSymbolAddress((void**)&bp_h,   g_bp_h);   cudaGetSymbolAddress((void**)&bp_l,   g_bp_l);

    auto spl = [](const float* src, __nv_bfloat16* h, __nv_bfloat16* l, int n) {
        int n4 = n / 4;
        split_kernel<<<(n4 + 255) / 256, 256>>>(src, h, l, n4);
    };
    spl(pe,   pe_h, pe_l, MTOT * DIM);
    spl(bp,   bp_h, bp_l, SEQ * DIM);
    spl(Wout, wo_h, wo_l, NLAYER * DIM * DIM);
    spl(W1,   w1_h, w1_l, NLAYER * MLPD * DIM);
    spl(W2,   w2_h, w2_l, NLAYER * DIM * MLPD);
    {
        int q = NLAYER * DIM * DIM / 4;
        split_wv_kernel<<<(q + 255) / 256, 256>>>(Wqkv, wv_h, wv_l);
    }

    const float scale = 0.03608439182435161f;   // 768^-0.5

    // dots = pe @ bp^T * scale  -> fp32 [8192,1024]
    mm_kernel<0><<<dim3(SEQ / BN, MTOT / BM, 1), 256, SMEM_SZ>>>(
        pe_h, pe_l, DIM, 0, bp_h, bp_l, DIM, 0,
        dots, nullptr, nullptr, SEQ, 0, DIM, nullptr, nullptr, scale);
    softmax_kernel<<<MTOT, 256>>>(dots, attn_h, attn_l);

    const float* xc = x;
    for (int l = 0; l < NLAYER; ++l) {
        const long long wOff  = (long long)l * DIM * DIM;
        const long long w1Off = (long long)l * MLPD * DIM;

        ln_kernel<<<MTOT, 256>>>(xc, xn_h, xn_l, ln1w + l * DIM, ln1b + l * DIM);

        // vT[c, token] = Wv @ xn^T : M=768, N=8192 -> split
        mm_kernel<1><<<dim3(MTOT / BN, DIM / BM, 1), 256, SMEM_SZ>>>(
            wv_h + wOff, wv_l + wOff, DIM, 0, xn_h, xn_l, DIM, 0,
            nullptr, vT_h, vT_l, MTOT, 0, DIM, nullptr, nullptr, 1.f);

        // av[b] = attn[b] @ v[b] : per batch M=1024, N=768, K=1024 -> split
        mm_kernel<1><<<dim3(DIM / BN, SEQ / BM, BATCH), 256, SMEM_SZ>>>(
            attn_h, attn_l, SEQ, (long long)SEQ * SEQ,
            vT_h, vT_l, MTOT, SEQ,
            nullptr, av_h, av_l, DIM, (long long)SEQ * DIM, SEQ, nullptr, nullptr, 1.f);

        // o = av @ Wout^T + bout : fp32
        mm_kernel<2><<<dim3(DIM / BN, MTOT / BM, 1), 256, SMEM_SZ>>>(
            av_h, av_l, DIM, 0, wo_h + wOff, wo_l + wOff, DIM, 0,
            o, nullptr, nullptr, DIM, 0, DIM, bout + l * DIM, nullptr, 1.f);

        ln_kernel<<<MTOT, 256>>>(o, y_h, y_l, ln2w + l * DIM, ln2b + l * DIM);

        // h1 = gelu(y @ W1^T + b1) -> split
        mm_kernel<3><<<dim3(MLPD / BN, MTOT / BM, 1), 256, SMEM_SZ>>>(
            y_h, y_l, DIM, 0, w1_h + w1Off, w1_l + w1Off, DIM, 0,
            nullptr, h1_h, h1_l, MLPD, 0, DIM, b1 + l * MLPD, nullptr, 1.f);

        // x' = h1 @ W2^T + b2 + o : fp32
        float* xdst = (l == NLAYER - 1) ? (float*)d_out : xb;
        mm_kernel<4><<<dim3(DIM / BN, MTOT / BM, 1), 256, SMEM_SZ>>>(
            h1_h, h1_l, MLPD, 0, w2_h + w1Off, w2_l + w1Off, MLPD, 0,
            xdst, nullptr, nullptr, DIM, 0, MLPD, b2 + l * DIM, o, 1.f);
        xc = xdst;
    }
}

// round 4
// speedup vs baseline: 3.6461x; 1.3640x over previous
#include <cuda_runtime.h>
#include <cuda_bf16.h>
#include <cstdint>
#include <math.h>

// ---------------------------------------------------------------------------
// SplitTransformer, bf16x3 split-precision GEMMs on mma.sync (HMMA).
// Round 4: KC=64, 3-stage cp.async pipeline, 1 sync/iter, XOR-swizzled smem
// (no padding), CTA rasterization for L2 reuse.
// B=8, N=1024, D=768, H=12, DH=64, L=4, MLP=3072
// ---------------------------------------------------------------------------

#define BATCH 8
#define SEQ   1024
#define DIM   768
#define NLAYER 4
#define MLPD  3072
#define MTOT  (BATCH*SEQ)   // 8192

#define BM 128
#define BN 128
#define KC 64               // bf16 k elements per pipeline stage (=128B row)

#define TILE_SZ   (128 * 128)               // 16384 B (128 rows x 128B, swizzled)
#define STAGE_SZ  (4 * TILE_SZ)             // Ah, Al, Bh, Bl = 64KB
#define NSTAGE    3
#define SMEM_SZ   (NSTAGE * STAGE_SZ)       // 192KB

// ---------------- scratch (__device__ globals; no cudaMalloc) --------------
__device__ float          g_dots[MTOT * SEQ];
__device__ __nv_bfloat16  g_attn_h[MTOT * SEQ], g_attn_l[MTOT * SEQ];
__device__ __nv_bfloat16  g_xn_h[MTOT * DIM],  g_xn_l[MTOT * DIM];
__device__ __nv_bfloat16  g_vT_h[DIM * MTOT],  g_vT_l[DIM * MTOT];   // [768, 8192]
__device__ __nv_bfloat16  g_av_h[MTOT * DIM],  g_av_l[MTOT * DIM];
__device__ float          g_o  [MTOT * DIM];
__device__ __nv_bfloat16  g_y_h[MTOT * DIM],   g_y_l[MTOT * DIM];
__device__ __nv_bfloat16  g_h1_h[MTOT * MLPD], g_h1_l[MTOT * MLPD];
__device__ float          g_xb [MTOT * DIM];
__device__ __nv_bfloat16  g_wv_h[NLAYER*DIM*DIM],   g_wv_l[NLAYER*DIM*DIM];
__device__ __nv_bfloat16  g_wo_h[NLAYER*DIM*DIM],   g_wo_l[NLAYER*DIM*DIM];
__device__ __nv_bfloat16  g_w1_h[NLAYER*MLPD*DIM],  g_w1_l[NLAYER*MLPD*DIM];
__device__ __nv_bfloat16  g_w2_h[NLAYER*DIM*MLPD],  g_w2_l[NLAYER*DIM*MLPD];
__device__ __nv_bfloat16  g_pe_h[MTOT * DIM],  g_pe_l[MTOT * DIM];
__device__ __nv_bfloat16  g_bp_h[SEQ * DIM],   g_bp_l[SEQ * DIM];

// ---------------- PTX helpers (baseline compute_103-legal) -----------------
__device__ __forceinline__ uint32_t smem_u32(const void* p) {
    uint32_t a;
    asm("{ .reg .u64 t; cvta.to.shared.u64 t, %1; cvt.u32.u64 %0, t; }" : "=r"(a) : "l"(p));
    return a;
}
__device__ __forceinline__ void cpa16(uint32_t s, const void* g) {
    asm volatile("cp.async.cg.shared.global [%0], [%1], 16;" :: "r"(s), "l"(g));
}
__device__ __forceinline__ void cp_commit() {
    asm volatile("cp.async.commit_group;" ::: "memory");
}
template<int N> __device__ __forceinline__ void cp_wait() {
    asm volatile("cp.async.wait_group %0;" :: "n"(N) : "memory");
}
__device__ __forceinline__ void ldsm4(uint32_t* r, uint32_t a) {
    asm volatile("ldmatrix.sync.aligned.m8n8.x4.shared.b16 {%0,%1,%2,%3}, [%4];"
        : "=r"(r[0]), "=r"(r[1]), "=r"(r[2]), "=r"(r[3]) : "r"(a));
}
__device__ __forceinline__ void mma16816(float* c, const uint32_t* a, const uint32_t* b) {
    asm volatile("mma.sync.aligned.m16n8k16.row.col.f32.bf16.bf16.f32 "
        "{%0,%1,%2,%3}, {%4,%5,%6,%7}, {%8,%9}, {%0,%1,%2,%3};"
        : "+f"(c[0]), "+f"(c[1]), "+f"(c[2]), "+f"(c[3])
        : "r"(a[0]), "r"(a[1]), "r"(a[2]), "r"(a[3]), "r"(b[0]), "r"(b[1]));
}
__device__ __forceinline__ void split2(float v, __nv_bfloat16& h, __nv_bfloat16& l) {
    h = __float2bfloat16_rn(v);
    l = __float2bfloat16_rn(v - __bfloat162float(h));
}

// ---------------------------------------------------------------------------
// EPI: 0 = scale -> fp32 ; 1 = split bf16 hi/lo ; 2 = bias -> fp32 ;
//      3 = bias+gelu -> split ; 4 = bias+residual -> fp32
// C = A[M,K] * B[N,K]^T with bf16x3 split precision (Ah*Bh + Ah*Bl + Al*Bh).
// ---------------------------------------------------------------------------
template<int EPI>
__global__ __launch_bounds__(256)
void mm_kernel(const __nv_bfloat16* __restrict__ Ah, const __nv_bfloat16* __restrict__ Al,
               int ldA, long long sAz,
               const __nv_bfloat16* __restrict__ Bh, const __nv_bfloat16* __restrict__ Bl,
               int ldB, long long sBz,
               float* __restrict__ Cf, __nv_bfloat16* __restrict__ Ch,
               __nv_bfloat16* __restrict__ Cl, int ldC, long long sCz,
               int Kdim, const float* __restrict__ bias, const float* __restrict__ res,
               float scale)
{
    extern __shared__ char smem_raw[];
    const int bz = blockIdx.z;
    Ah += (long long)bz * sAz;  Al += (long long)bz * sAz;
    Bh += (long long)bz * sBz;  Bl += (long long)bz * sBz;
    const long long coff = (long long)bz * sCz;

    // CTA rasterization: groups of 8 row-tiles share one B column tile
    int bx, by;
    {
        const int gx = gridDim.x, gy = gridDim.y;
        const int bid = blockIdx.y * gx + blockIdx.x;
        const int GRP = 8;
        const int per = GRP * gx;
        const int grp = bid / per;
        const int rem = bid - grp * per;
        const int gh  = min(GRP, gy - grp * GRP);
        by = grp * GRP + rem % gh;
        bx = rem / gh;
    }
    const int m0 = by * BM;
    const int n0 = bx * BN;

    const int tid = threadIdx.x;
    const int wid = tid >> 5, lid = tid & 31;
    const uint32_t sb = smem_u32(smem_raw);

    const int wm = wid & 1;          // 2 m-tiles of 64
    const int wn = wid >> 1;         // 4 n-tiles of 32
    const int arow = lid & 15;
    const int aSel = lid >> 4;             // 0/1 -> 16B chunk within k16
    const int brow = (lid & 7) + ((lid >> 4) & 1) * 8;
    const int bSel = (lid >> 3) & 1;
    const int swz  = lid & 7;              // row&7 component for xor swizzle

    float acc[4][4][4];
    #pragma unroll
    for (int mi = 0; mi < 4; mi++)
        #pragma unroll
        for (int ni = 0; ni < 4; ni++)
            #pragma unroll
            for (int q = 0; q < 4; q++) acc[mi][ni][q] = 0.f;

    const int T = Kdim >> 6;

    // ---- issue one KC=64 stage: 4 tiles (Ah, Al, Bh, Bl), swizzled ----
    auto issue = [&](int kt) {
        const uint32_t sbuf = sb + (uint32_t)(kt % NSTAGE) * STAGE_SZ;
        const int k0 = kt * KC;
        #pragma unroll
        for (int i = 0; i < 4; i++) {
            const int u = tid + i * 256;
            const int r = u >> 3, c = u & 7;
            const uint32_t soff = (uint32_t)(r << 7) + (uint32_t)((c ^ (r & 7)) << 4);
            const size_t ga = (size_t)(m0 + r) * ldA + k0 + c * 8;
            const size_t gb = (size_t)(n0 + r) * ldB + k0 + c * 8;
            cpa16(sbuf + soff,               Ah + ga);
            cpa16(sbuf + TILE_SZ + soff,     Al + ga);
            cpa16(sbuf + 2 * TILE_SZ + soff, Bh + gb);
            cpa16(sbuf + 3 * TILE_SZ + soff, Bl + gb);
        }
        cp_commit();
    };

    issue(0);
    if (T > 1) issue(1);

    for (int kt = 0; kt < T; kt++) {
        if (kt + 1 < T) cp_wait<1>(); else cp_wait<0>();
        __syncthreads();

        const uint32_t sbuf = sb + (uint32_t)(kt % NSTAGE) * STAGE_SZ;
        const uint32_t aB  = sbuf;
        const uint32_t alB = sbuf + TILE_SZ;
        const uint32_t bB  = sbuf + 2 * TILE_SZ;
        const uint32_t blB = sbuf + 3 * TILE_SZ;

        #pragma unroll
        for (int kk = 0; kk < 4; kk++) {           // four k16 slices of KC=64
            uint32_t ah[4][4], al_[4][4];
            #pragma unroll
            for (int mi = 0; mi < 4; mi++) {
                const uint32_t off = (uint32_t)((wm * 64 + mi * 16 + arow) << 7)
                                   + (uint32_t)((((kk * 2 + aSel) ^ swz)) << 4);
                ldsm4(ah[mi],  aB  + off);
                ldsm4(al_[mi], alB + off);
            }
            uint32_t bh[2][4], bl[2][4];
            #pragma unroll
            for (int nj = 0; nj < 2; nj++) {
                const uint32_t off = (uint32_t)((wn * 32 + nj * 16 + brow) << 7)
                                   + (uint32_t)((((kk * 2 + bSel) ^ swz)) << 4);
                ldsm4(bh[nj], bB  + off);
                ldsm4(bl[nj], blB + off);
            }
            #pragma unroll
            for (int mi = 0; mi < 4; mi++)
                #pragma unroll
                for (int ni = 0; ni < 4; ni++) {
                    const uint32_t* bhp = &bh[ni >> 1][(ni & 1) * 2];
                    const uint32_t* blp = &bl[ni >> 1][(ni & 1) * 2];
                    mma16816(acc[mi][ni], ah[mi],  bhp);
                    mma16816(acc[mi][ni], ah[mi],  blp);
                    mma16816(acc[mi][ni], al_[mi], bhp);
                }
        }
        if (kt + 2 < T) issue(kt + 2);
    }

    // ---- epilogue ----
    const int l4 = lid >> 2;
    const int lp = (lid & 3) * 2;
    #pragma unroll
    for (int mi = 0; mi < 4; mi++) {
        #pragma unroll
        for (int ni = 0; ni < 4; ni++) {
            const int col  = n0 + wn * 32 + ni * 8 + lp;
            const int rowA = m0 + wm * 64 + mi * 16 + l4;
            float* a = acc[mi][ni];
            float b0 = 0.f, b1 = 0.f;
            if (EPI == 2 || EPI == 3 || EPI == 4) {
                b0 = __ldg(bias + col);
                b1 = __ldg(bias + col + 1);
            }
            #pragma unroll
            for (int h = 0; h < 2; h++) {
                const int row = rowA + h * 8;
                float v0 = a[h * 2], v1 = a[h * 2 + 1];
                if (EPI == 0) { v0 *= scale; v1 *= scale; }
                if (EPI == 2 || EPI == 3 || EPI == 4) { v0 += b0; v1 += b1; }
                if (EPI == 3) {
                    v0 = 0.5f * v0 * (1.0f + erff(v0 * 0.70710678118654752f));
                    v1 = 0.5f * v1 * (1.0f + erff(v1 * 0.70710678118654752f));
                }
                const size_t cbase = (size_t)row * ldC + col + coff;
                if (EPI == 4) {
                    float2 rr = *(const float2*)(res + cbase);
                    v0 += rr.x; v1 += rr.y;
                }
                if (EPI == 0 || EPI == 2 || EPI == 4) {
                    *(float2*)(Cf + cbase) = make_float2(v0, v1);
                } else {
                    __nv_bfloat16 h0, l0, h1_, l1_;
                    split2(v0, h0, l0); split2(v1, h1_, l1_);
                    __nv_bfloat162 hh; hh.x = h0; hh.y = h1_;
                    __nv_bfloat162 ll; ll.x = l0; ll.y = l1_;
                    *(__nv_bfloat162*)(Ch + cbase) = hh;
                    *(__nv_bfloat162*)(Cl + cbase) = ll;
                }
            }
        }
    }
}

// ---------------------------------------------------------------------------
// fp32 -> bf16 hi/lo split (contiguous)
__global__ void split_kernel(const float* __restrict__ in, __nv_bfloat16* __restrict__ h,
                             __nv_bfloat16* __restrict__ l, int n4)
{
    int i = blockIdx.x * blockDim.x + threadIdx.x;
    if (i >= n4) return;
    float4 v = *(const float4*)(in + i * 4);
    __nv_bfloat16 h0,l0,h1,l1,h2,l2,h3,l3;
    split2(v.x,h0,l0); split2(v.y,h1,l1); split2(v.z,h2,l2); split2(v.w,h3,l3);
    __nv_bfloat162 a; a.x=h0; a.y=h1; __nv_bfloat162 b; b.x=h2; b.y=h3;
    __nv_bfloat162 c; c.x=l0; c.y=l1; __nv_bfloat162 d; d.x=l2; d.y=l3;
    *(uint2*)(h + i * 4) = make_uint2(*(uint32_t*)&a, *(uint32_t*)&b);
    *(uint2*)(l + i * 4) = make_uint2(*(uint32_t*)&c, *(uint32_t*)&d);
}

// Wv slice split: Wqkv[l, 1536:2304, :] for l in 0..3
__global__ void split_wv_kernel(const float* __restrict__ Wqkv,
                                __nv_bfloat16* __restrict__ h, __nv_bfloat16* __restrict__ l)
{
    int i = blockIdx.x * blockDim.x + threadIdx.x;
    const int per = DIM * DIM / 4;
    if (i >= NLAYER * per) return;
    int li = i / per, rem = i - li * per;
    const float* src = Wqkv + (size_t)li * 3 * DIM * DIM + (size_t)2 * DIM * DIM + rem * 4;
    float4 v = *(const float4*)src;
    __nv_bfloat16 h0,l0,h1,l1,h2,l2,h3,l3;
    split2(v.x,h0,l0); split2(v.y,h1,l1); split2(v.z,h2,l2); split2(v.w,h3,l3);
    __nv_bfloat162 a; a.x=h0; a.y=h1; __nv_bfloat162 b; b.x=h2; b.y=h3;
    __nv_bfloat162 c; c.x=l0; c.y=l1; __nv_bfloat162 d; d.x=l2; d.y=l3;
    *(uint2*)(h + i * 4) = make_uint2(*(uint32_t*)&a, *(uint32_t*)&b);
    *(uint2*)(l + i * 4) = make_uint2(*(uint32_t*)&c, *(uint32_t*)&d);
}

// ---------------------------------------------------------------------------
// softmax over 1024 cols, fp32 in -> bf16 hi/lo out
__global__ void softmax_kernel(const float* __restrict__ dots,
                               __nv_bfloat16* __restrict__ oh, __nv_bfloat16* __restrict__ ol)
{
    const size_t row = blockIdx.x;
    const float* p = dots + row * SEQ;
    const int t = threadIdx.x;

    float4 v = *(const float4*)(p + t * 4);
    float mx = fmaxf(fmaxf(v.x, v.y), fmaxf(v.z, v.w));
    __shared__ float sh[8];
    #pragma unroll
    for (int o = 16; o; o >>= 1) mx = fmaxf(mx, __shfl_xor_sync(0xffffffffu, mx, o));
    if ((t & 31) == 0) sh[t >> 5] = mx;
    __syncthreads();
    if (t < 32) {
        float m = (t < 8) ? sh[t] : -3.4e38f;
        #pragma unroll
        for (int o = 4; o; o >>= 1) m = fmaxf(m, __shfl_xor_sync(0xffffffffu, m, o));
        if (t == 0) sh[0] = m;
    }
    __syncthreads();
    mx = sh[0];
    __syncthreads();

    v.x = expf(v.x - mx); v.y = expf(v.y - mx);
    v.z = expf(v.z - mx); v.w = expf(v.w - mx);
    float s = v.x + v.y + v.z + v.w;
    #pragma unroll
    for (int o = 16; o; o >>= 1) s += __shfl_xor_sync(0xffffffffu, s, o);
    if ((t & 31) == 0) sh[t >> 5] = s;
    __syncthreads();
    if (t < 32) {
        float m = (t < 8) ? sh[t] : 0.f;
        #pragma unroll
        for (int o = 4; o; o >>= 1) m += __shfl_xor_sync(0xffffffffu, m, o);
        if (t == 0) sh[0] = m;
    }
    __syncthreads();
    const float inv = 1.0f / sh[0];
    v.x *= inv; v.y *= inv; v.z *= inv; v.w *= inv;

    __nv_bfloat16 h0,l0,h1,l1,h2,l2,h3,l3;
    split2(v.x,h0,l0); split2(v.y,h1,l1); split2(v.z,h2,l2); split2(v.w,h3,l3);
    __nv_bfloat162 a; a.x=h0; a.y=h1; __nv_bfloat162 b; b.x=h2; b.y=h3;
    __nv_bfloat162 c; c.x=l0; c.y=l1; __nv_bfloat162 d; d.x=l2; d.y=l3;
    *(uint2*)(oh + row * SEQ + t * 4) = make_uint2(*(uint32_t*)&a, *(uint32_t*)&b);
    *(uint2*)(ol + row * SEQ + t * 4) = make_uint2(*(uint32_t*)&c, *(uint32_t*)&d);
}

// ---------------------------------------------------------------------------
// LayerNorm(768) -> bf16 hi/lo
__global__ void ln_kernel(const float* __restrict__ in, __nv_bfloat16* __restrict__ oh,
                          __nv_bfloat16* __restrict__ ol,
                          const float* __restrict__ w, const float* __restrict__ b)
{
    const size_t row = blockIdx.x;
    const float* p = in + row * DIM;
    const int t = threadIdx.x;

    float x0 = p[t], x1 = p[t + 256], x2 = p[t + 512];
    float s  = x0 + x1 + x2;
    float ss = x0 * x0 + x1 * x1 + x2 * x2;

    __shared__ float shs[8], shss[8];
    #pragma unroll
    for (int o = 16; o; o >>= 1) {
        s  += __shfl_xor_sync(0xffffffffu, s,  o);
        ss += __shfl_xor_sync(0xffffffffu, ss, o);
    }
    if ((t & 31) == 0) { shs[t >> 5] = s; shss[t >> 5] = ss; }
    __syncthreads();
    if (t < 32) {
        s  = (t < 8) ? shs[t]  : 0.f;
        ss = (t < 8) ? shss[t] : 0.f;
        #pragma unroll
        for (int o = 4; o; o >>= 1) {
            s  += __shfl_xor_sync(0xffffffffu, s,  o);
            ss += __shfl_xor_sync(0xffffffffu, ss, o);
        }
        if (t == 0) { shs[0] = s; shss[0] = ss; }
    }
    __syncthreads();
    const float mean = shs[0] * (1.f / DIM);
    const float var  = shss[0] * (1.f / DIM) - mean * mean;
    const float r    = rsqrtf(var + 1e-5f);

    #pragma unroll
    for (int q = 0; q < 3; q++) {
        int idx = t + q * 256;
        float y = (((q == 0) ? x0 : (q == 1) ? x1 : x2) - mean) * r * w[idx] + b[idx];
        __nv_bfloat16 h, l; split2(y, h, l);
        oh[row * DIM + idx] = h;
        ol[row * DIM + idx] = l;
    }
}

// ---------------------------------------------------------------------------
extern "C" void kernel_launch(void* const* d_in, const int* in_sizes, int n_in,
                              void* d_out, int out_size)
{
    const float* x    = (const float*)d_in[0];
    const float* pe   = (const float*)d_in[1];
    const float* bp   = (const float*)d_in[2];
    const float* ln1w = (const float*)d_in[3];
    const float* ln1b = (const float*)d_in[4];
    const float* Wqkv = (const float*)d_in[5];
    const float* Wout = (const float*)d_in[6];
    const float* bout = (const float*)d_in[7];
    const float* ln2w = (const float*)d_in[8];
    const float* ln2b = (const float*)d_in[9];
    const float* W1   = (const float*)d_in[10];
    const float* b1   = (const float*)d_in[11];
    const float* W2   = (const float*)d_in[12];
    const float* b2   = (const float*)d_in[13];

    cudaFuncSetAttribute(mm_kernel<0>, cudaFuncAttributeMaxDynamicSharedMemorySize, SMEM_SZ);
    cudaFuncSetAttribute(mm_kernel<1>, cudaFuncAttributeMaxDynamicSharedMemorySize, SMEM_SZ);
    cudaFuncSetAttribute(mm_kernel<2>, cudaFuncAttributeMaxDynamicSharedMemorySize, SMEM_SZ);
    cudaFuncSetAttribute(mm_kernel<3>, cudaFuncAttributeMaxDynamicSharedMemorySize, SMEM_SZ);
    cudaFuncSetAttribute(mm_kernel<4>, cudaFuncAttributeMaxDynamicSharedMemorySize, SMEM_SZ);

    float *dots, *o, *xb;
    __nv_bfloat16 *attn_h, *attn_l, *xn_h, *xn_l, *vT_h, *vT_l, *av_h, *av_l;
    __nv_bfloat16 *y_h, *y_l, *h1_h, *h1_l;
    __nv_bfloat16 *wv_h, *wv_l, *wo_h, *wo_l, *w1_h, *w1_l, *w2_h, *w2_l;
    __nv_bfloat16 *pe_h, *pe_l, *bp_h, *bp_l;
    cudaGetSymbolAddress((void**)&dots,   g_dots);
    cudaGetSymbolAddress((void**)&attn_h, g_attn_h); cudaGetSymbolAddress((void**)&attn_l, g_attn_l);
    cudaGetSymbolAddress((void**)&xn_h,   g_xn_h);   cudaGetSymbolAddress((void**)&xn_l,   g_xn_l);
    cudaGetSymbolAddress((void**)&vT_h,   g_vT_h);   cudaGetSymbolAddress((void**)&vT_l,   g_vT_l);
    cudaGetSymbolAddress((void**)&av_h,   g_av_h);   cudaGetSymbolAddress((void**)&av_l,   g_av_l);
    cudaGetSymbolAddress((void**)&o,      g_o);
    cudaGetSymbolAddress((void**)&y_h,    g_y_h);    cudaGetSymbolAddress((void**)&y_l,    g_y_l);
    cudaGetSymbolAddress((void**)&h1_h,   g_h1_h);   cudaGetSymbolAddress((void**)&h1_l,   g_h1_l);
    cudaGetSymbolAddress((void**)&xb,     g_xb);
    cudaGetSymbolAddress((void**)&wv_h,   g_wv_h);   cudaGetSymbolAddress((void**)&wv_l,   g_wv_l);
    cudaGetSymbolAddress((void**)&wo_h,   g_wo_h);   cudaGetSymbolAddress((void**)&wo_l,   g_wo_l);
    cudaGetSymbolAddress((void**)&w1_h,   g_w1_h);   cudaGetSymbolAddress((void**)&w1_l,   g_w1_l);
    cudaGetSymbolAddress((void**)&w2_h,   g_w2_h);   cudaGetSymbolAddress((void**)&w2_l,   g_w2_l);
    cudaGetSymbolAddress((void**)&pe_h,   g_pe_h);   cudaGetSymbolAddress((void**)&pe_l,   g_pe_l);
    cudaGetSymbolAddress((void**)&bp_h,   g_bp_h);   cudaGetSymbolAddress((void**)&bp_l,   g_bp_l);

    auto spl = [](const float* src, __nv_bfloat16* h, __nv_bfloat16* l, int n) {
        int n4 = n / 4;
        split_kernel<<<(n4 + 255) / 256, 256>>>(src, h, l, n4);
    };
    // Launch order: 5 splits, then dots GEMM as launch #6 (ncu -s 5 -c 1 target)
    spl(pe,   pe_h, pe_l, MTOT * DIM);
    spl(bp,   bp_h, bp_l, SEQ * DIM);
    spl(Wout, wo_h, wo_l, NLAYER * DIM * DIM);
    spl(W1,   w1_h, w1_l, NLAYER * MLPD * DIM);
    spl(W2,   w2_h, w2_l, NLAYER * DIM * MLPD);

    const float scale = 0.03608439182435161f;   // 768^-0.5

    // dots = pe @ bp^T * scale  -> fp32 [8192,1024]
    mm_kernel<0><<<dim3(SEQ / BN, MTOT / BM, 1), 256, SMEM_SZ>>>(
        pe_h, pe_l, DIM, 0, bp_h, bp_l, DIM, 0,
        dots, nullptr, nullptr, SEQ, 0, DIM, nullptr, nullptr, scale);

    {
        int q = NLAYER * DIM * DIM / 4;
        split_wv_kernel<<<(q + 255) / 256, 256>>>(Wqkv, wv_h, wv_l);
    }
    softmax_kernel<<<MTOT, 256>>>(dots, attn_h, attn_l);

    const float* xc = x;
    for (int l = 0; l < NLAYER; ++l) {
        const long long wOff  = (long long)l * DIM * DIM;
        const long long w1Off = (long long)l * MLPD * DIM;

        ln_kernel<<<MTOT, 256>>>(xc, xn_h, xn_l, ln1w + l * DIM, ln1b + l * DIM);

        // vT[c, token] = Wv @ xn^T : M=768, N=8192 -> split
        mm_kernel<1><<<dim3(MTOT / BN, DIM / BM, 1), 256, SMEM_SZ>>>(
            wv_h + wOff, wv_l + wOff, DIM, 0, xn_h, xn_l, DIM, 0,
            nullptr, vT_h, vT_l, MTOT, 0, DIM, nullptr, nullptr, 1.f);

        // av[b] = attn[b] @ v[b] : per batch M=1024, N=768, K=1024 -> split
        mm_kernel<1><<<dim3(DIM / BN, SEQ / BM, BATCH), 256, SMEM_SZ>>>(
            attn_h, attn_l, SEQ, (long long)SEQ * SEQ,
            vT_h, vT_l, MTOT, SEQ,
            nullptr, av_h, av_l, DIM, (long long)SEQ * DIM, SEQ, nullptr, nullptr, 1.f);

        // o = av @ Wout^T + bout : fp32
        mm_kernel<2><<<dim3(DIM / BN, MTOT / BM, 1), 256, SMEM_SZ>>>(
            av_h, av_l, DIM, 0, wo_h + wOff, wo_l + wOff, DIM, 0,
            o, nullptr, nullptr, DIM, 0, DIM, bout + l * DIM, nullptr, 1.f);

        ln_kernel<<<MTOT, 256>>>(o, y_h, y_l, ln2w + l * DIM, ln2b + l * DIM);

        // h1 = gelu(y @ W1^T + b1) -> split
        mm_kernel<3><<<dim3(MLPD / BN, MTOT / BM, 1), 256, SMEM_SZ>>>(
            y_h, y_l, DIM, 0, w1_h + w1Off, w1_l + w1Off, DIM, 0,
            nullptr, h1_h, h1_l, MLPD, 0, DIM, b1 + l * MLPD, nullptr, 1.f);

        // x' = h1 @ W2^T + b2 + o : fp32
        float* xdst = (l == NLAYER - 1) ? (float*)d_out : xb;
        mm_kernel<4><<<dim3(DIM / BN, MTOT / BM, 1), 256, SMEM_SZ>>>(
            h1_h, h1_l, MLPD, 0, w2_h + w1Off, w2_l + w1Off, MLPD, 0,
            xdst, nullptr, nullptr, DIM, 0, MLPD, b2 + l * DIM, o, 1.f);
        xc = xdst;
    }
}